// round 12
// baseline (speedup 1.0000x reference)
#include <cuda_runtime.h>
#include <cuda_fp16.h>
#include <math.h>
#include <stdint.h>
#include <string.h>

// Problem dims
#define BATCH 8
#define ENS   16
#define NCIN  64
#define NCH   64
#define HW    4096
#define NBI   (BATCH*ENS)          // 128
#define NELEM ((size_t)NBI*NCH*HW) // 33,554,432

// Scratch (static device arrays -- allocation-free)
__device__ float g_V[NELEM];
__device__ float g_K[NELEM];               // raw conv output + bias (pre-SELU)
__device__ float g_Q[NELEM];               // raw conv output + bias (pre-SELU)
__device__ float g_Wgt[BATCH*NCH*ENS*ENS]; // softmaxed weights [b,c,i,j]

#define W_STRIDE   36    // half2 per W row (32 kpairs + pad)
__device__ __half2 g_Wh[192 * W_STRIDE];   // prepacked SMEM image (hi)
__device__ __half2 g_Wl[192 * W_STRIDE];   // prepacked SMEM image (lo)
__device__ float   g_bias3[192];

__device__ __forceinline__ float selu_f(float x) {
    const float scale = 1.0507009873554805f;
    const float alpha = 1.6732632423543772f;
    return x > 0.f ? scale * x : scale * alpha * expm1f(x);
}

__device__ __forceinline__ uint32_t h2u(__half2 v) {
    uint32_t r;
    memcpy(&r, &v, sizeof(r));
    return r;
}

__device__ __forceinline__ uint32_t smem_u32(const void* p) {
    return (uint32_t)__cvta_generic_to_shared(p);
}
__device__ __forceinline__ void cp16(void* dst_smem, const void* src) {
    uint32_t d = smem_u32(dst_smem);
    asm volatile("cp.async.cg.shared.global [%0], [%1], 16;" :: "r"(d), "l"(src));
}
#define CP_COMMIT()  asm volatile("cp.async.commit_group;" ::: "memory")
#define CP_WAIT(n)   asm volatile("cp.async.wait_group %0;" :: "n"(n) : "memory")

// fp16 MMA m16n8k16 (baseline PTX, valid on sm_103 non-'a' target)
__device__ __forceinline__ void mma_f16(float* c,
                                        uint32_t a0, uint32_t a1, uint32_t a2, uint32_t a3,
                                        uint32_t b0, uint32_t b1)
{
    asm volatile(
        "mma.sync.aligned.m16n8k16.row.col.f32.f16.f16.f32 "
        "{%0,%1,%2,%3}, {%4,%5,%6,%7}, {%8,%9}, {%0,%1,%2,%3};"
        : "+f"(c[0]), "+f"(c[1]), "+f"(c[2]), "+f"(c[3])
        : "r"(a0), "r"(a1), "r"(a2), "r"(a3), "r"(b0), "r"(b1));
}

// ldmatrix x4 (non-trans), baseline sm_75+ PTX
__device__ __forceinline__ void ldsm_x4(uint32_t& r0, uint32_t& r1,
                                        uint32_t& r2, uint32_t& r3, uint32_t addr)
{
    asm volatile("ldmatrix.sync.aligned.m8n8.x4.shared.b16 {%0,%1,%2,%3}, [%4];"
                 : "=r"(r0), "=r"(r1), "=r"(r2), "=r"(r3) : "r"(addr));
}

// ===========================================================================
// Kernel 0: prep — W3 fp16 hi/lo split into the exact SMEM image + bias.
// One block of 512 threads; runs once, ~2us.
// ===========================================================================
__global__ __launch_bounds__(512)
void prep_kernel(const float* __restrict__ Wv, const float* __restrict__ bv,
                 const float* __restrict__ Wk, const float* __restrict__ bk,
                 const float* __restrict__ Wq, const float* __restrict__ bq)
{
    const int tid = threadIdx.x;
    if (tid < 192) {
        g_bias3[tid] = tid < 64 ? bv[tid] : (tid < 128 ? bk[tid - 64] : bq[tid - 128]);
    }
    // zero pads for determinism
    #pragma unroll
    for (int j = 0; j < 2; j++) {
        int p = tid + j * 512;                // 192*4 = 768 pad half2s
        if (p < 192 * 4) {
            int n = p >> 2, k = p & 3;
            g_Wh[n * W_STRIDE + 32 + k] = __floats2half2_rn(0.f, 0.f);
            g_Wl[n * W_STRIDE + 32 + k] = __floats2half2_rn(0.f, 0.f);
        }
    }
    #pragma unroll
    for (int j = 0; j < 12; j++) {
        int idx = tid + j * 512;              // 6144 kpairs
        int n = idx >> 5, kp = idx & 31;
        const float* Wsrc = n < 64 ? &Wv[n * NCIN] :
                            n < 128 ? &Wk[(n - 64) * NCIN] : &Wq[(n - 128) * NCIN];
        float w0 = Wsrc[kp * 2], w1 = Wsrc[kp * 2 + 1];
        __half2 h = __floats2half2_rn(w0, w1);
        __half2 l = __floats2half2_rn(w0 - __low2float(h), w1 - __high2float(h));
        g_Wh[n * W_STRIDE + kp] = h;
        g_Wl[n * W_STRIDE + kp] = l;
    }
}

// ===========================================================================
// Kernel 1: fused 3-conv via FP16-split (2-way) mma.sync m16n8k16 + ldmatrix.
// Per (b,i): Out[192 ch, 4096 hw] = W3[192,64] @ X[64,4096]
// Bias folded into accumulator init; NO selu here (gram applies it).
// CTA: 512 thr (16 warps, 4m x 4n), tile 192 x 128 hw, TPC hw-tiles per CTA.
// ===========================================================================
#define THREADS    512
#define TPC        4
#define XN_STRIDE  36    // half2 per X n-row
#define RAW_STRIDE 132   // float per raw X cin-row

// SMEM byte offsets
#define OFF_WH    0                              // 192*36*4 = 27648
#define OFF_WL    27648
#define OFF_RAW   55296                          // 64*132*4 = 33792
#define OFF_XH0   89088                          // 128*36*4 = 18432
#define OFF_XL0   107520
#define OFF_XH1   125952
#define OFF_XL1   144384
#define OFF_BIAS  162816                         // 192*4
#define SMEM_BYTES 163584
#define XL_DELTA  (OFF_XL0 - OFF_XH0)            // 18432

// Issue this thread's cp.asyncs for one X tile (row-major raw staging)
__device__ __forceinline__ void stage_tile(float* __restrict__ rawp,
                                           const float* __restrict__ xb,
                                           int hw0, int tid)
{
    #pragma unroll
    for (int j = 0; j < 2; j++) {
        int u = tid + j * THREADS;         // 1024 (kp, c4) units
        int kp = u >> 5, c4 = u & 31;
        cp16(&rawp[(2 * kp) * RAW_STRIDE + c4 * 4],
             xb + (size_t)(2 * kp) * HW + hw0 + c4 * 4);
        cp16(&rawp[(2 * kp + 1) * RAW_STRIDE + c4 * 4],
             xb + (size_t)(2 * kp + 1) * HW + hw0 + c4 * 4);
    }
    CP_COMMIT();
}

// Convert raw [64 cin][128 hw] fp32 -> n-major hi/lo fp16.
__device__ __forceinline__ void convert_n(const float* __restrict__ rawp,
                                          __half2* __restrict__ Xh,
                                          __half2* __restrict__ Xl,
                                          int tid)
{
    #pragma unroll
    for (int j = 0; j < 2; j++) {
        int u = tid + j * THREADS;         // 1024 units
        int n = u & 127, kpb = u >> 7;
        const float* col = rawp + (size_t)(8 * kpb) * RAW_STRIDE + n;
        float r0 = col[0 * RAW_STRIDE], r1 = col[1 * RAW_STRIDE];
        float r2 = col[2 * RAW_STRIDE], r3 = col[3 * RAW_STRIDE];
        float r4 = col[4 * RAW_STRIDE], r5 = col[5 * RAW_STRIDE];
        float r6 = col[6 * RAW_STRIDE], r7 = col[7 * RAW_STRIDE];
        __half2 h0 = __floats2half2_rn(r0, r1);
        __half2 h1 = __floats2half2_rn(r2, r3);
        __half2 h2 = __floats2half2_rn(r4, r5);
        __half2 h3 = __floats2half2_rn(r6, r7);
        __half2 l0 = __floats2half2_rn(r0 - __low2float(h0), r1 - __high2float(h0));
        __half2 l1 = __floats2half2_rn(r2 - __low2float(h1), r3 - __high2float(h1));
        __half2 l2 = __floats2half2_rn(r4 - __low2float(h2), r5 - __high2float(h2));
        __half2 l3 = __floats2half2_rn(r6 - __low2float(h3), r7 - __high2float(h3));
        *(uint4*)&Xh[n * XN_STRIDE + 4 * kpb] =
            make_uint4(h2u(h0), h2u(h1), h2u(h2), h2u(h3));
        *(uint4*)&Xl[n * XN_STRIDE + 4 * kpb] =
            make_uint4(h2u(l0), h2u(l1), h2u(l2), h2u(l3));
    }
}

__global__ __launch_bounds__(THREADS, 1)
void conv3_mma_kernel(const float* __restrict__ x)
{
    extern __shared__ char smem[];
    const uint32_t sbase = smem_u32(smem);
    float*   rawp = (float*)(smem + OFF_RAW);
    __half2* XhB[2] = { (__half2*)(smem + OFF_XH0), (__half2*)(smem + OFF_XH1) };
    __half2* XlB[2] = { (__half2*)(smem + OFF_XL0), (__half2*)(smem + OFF_XL1) };
    float*   sbias = (float*)(smem + OFF_BIAS);

    const int tid  = threadIdx.x;
    const int wid  = tid >> 5;
    const int lane = tid & 31;
    const int g    = lane >> 2;     // groupID
    const int tig  = lane & 3;      // threadID_in_group

    const int bi = blockIdx.x;      // 0..127
    const int tg = blockIdx.y;      // 0..7
    const float* xb = x + (size_t)bi * NCIN * HW;

    // ---- stage tile0 ----
    stage_tile(rawp, xb, tg * TPC * 128, tid);

    // ---- async-copy prepacked W images + bias into SMEM ----
    {
        const float4* srcH = (const float4*)g_Wh;
        const float4* srcL = (const float4*)g_Wl;
        char* dstH = smem + OFF_WH;
        char* dstL = smem + OFF_WL;
        #pragma unroll
        for (int j = 0; j < 4; j++) {
            int idx = tid + j * THREADS;       // 1728 float4 per image
            if (idx < 1728) {
                cp16(dstH + idx * 16, srcH + idx);
                cp16(dstL + idx * 16, srcL + idx);
            }
        }
        if (tid < 48) cp16(smem + OFF_BIAS + tid * 16, (const float4*)g_bias3 + tid);
        CP_COMMIT();
    }

    CP_WAIT(0);
    __syncthreads();                           // staging + W + bias complete
    convert_n(rawp, XhB[0], XlB[0], tid);
    __syncthreads();                           // tile0 hi/lo ready

    const int mrow0 = (wid & 3) * 48;   // warp channel-rows base (3 x m16)
    const int ncol0 = (wid >> 2) * 32;  // warp hw-cols base (4 x n8)

    // per-thread bias registers for accumulator init
    float b_lo[3], b_hi[3];
    #pragma unroll
    for (int ms = 0; ms < 3; ms++) {
        b_lo[ms] = sbias[mrow0 + ms * 16 + g];
        b_hi[ms] = sbias[mrow0 + ms * 16 + 8 + g];
    }

    // ---- precomputed ldmatrix addresses (bytes) ----
    const int rowA_off = ((lane >> 3) & 1) * 8 + (lane & 7);
    const int kpA      = (lane >> 4) * 4;
    uint32_t addrAh[3], addrAl[3];
    #pragma unroll
    for (int ms = 0; ms < 3; ms++) {
        int row = mrow0 + ms * 16 + rowA_off;
        addrAh[ms] = sbase + OFF_WH + (uint32_t)(row * W_STRIDE + kpA) * 4;
        addrAl[ms] = addrAh[ms] + (OFF_WL - OFF_WH);
    }
    const int nB_off = ((lane >> 4) & 1) * 8 + (lane & 7);
    const int kpB    = ((lane >> 3) & 1) * 4;
    uint32_t relB[2];
    #pragma unroll
    for (int p = 0; p < 2; p++) {
        int n = ncol0 + p * 16 + nB_off;
        relB[p] = (uint32_t)(n * XN_STRIDE + kpB) * 4;
    }

    for (int t = 0; t < TPC; t++) {
        const int hw0 = (tg * TPC + t) * 128;

        // prefetch next raw tile (overlaps with MMA below)
        if (t + 1 < TPC) stage_tile(rawp, xb, hw0 + 128, tid);

        const uint32_t xh_base = sbase + ((t & 1) ? OFF_XH1 : OFF_XH0);
        const uint32_t xl_base = xh_base + XL_DELTA;

        // accumulators pre-loaded with bias (MMA accumulates on top)
        float acc[3][4][4];
        #pragma unroll
        for (int ms = 0; ms < 3; ms++)
            #pragma unroll
            for (int ns = 0; ns < 4; ns++) {
                acc[ms][ns][0] = b_lo[ms]; acc[ms][ns][1] = b_lo[ms];
                acc[ms][ns][2] = b_hi[ms]; acc[ms][ns][3] = b_hi[ms];
            }

        #pragma unroll
        for (int ks = 0; ks < 4; ks++) {
            const uint32_t ko = (uint32_t)ks * 32;   // 8 half2 per ks
            uint32_t bh[4][2], bl[4][2];
            ldsm_x4(bh[0][0], bh[0][1], bh[1][0], bh[1][1], xh_base + relB[0] + ko);
            ldsm_x4(bh[2][0], bh[2][1], bh[3][0], bh[3][1], xh_base + relB[1] + ko);
            ldsm_x4(bl[0][0], bl[0][1], bl[1][0], bl[1][1], xl_base + relB[0] + ko);
            ldsm_x4(bl[2][0], bl[2][1], bl[3][0], bl[3][1], xl_base + relB[1] + ko);

            #pragma unroll
            for (int ms = 0; ms < 3; ms++) {
                uint32_t ah0, ah1, ah2, ah3, al0, al1, al2, al3;
                ldsm_x4(ah0, ah1, ah2, ah3, addrAh[ms] + ko);
                ldsm_x4(al0, al1, al2, al3, addrAl[ms] + ko);
                #pragma unroll
                for (int ns = 0; ns < 4; ns++) {
                    mma_f16(acc[ms][ns], ah0, ah1, ah2, ah3, bh[ns][0], bh[ns][1]);
                    mma_f16(acc[ms][ns], ah0, ah1, ah2, ah3, bl[ns][0], bl[ns][1]);
                    mma_f16(acc[ms][ns], al0, al1, al2, al3, bh[ns][0], bh[ns][1]);
                }
            }
        }

        // ---- epilogue: pure stores (bias already in acc; no selu here) ----
        {
            float* baseV = g_V + (size_t)bi * NCH * HW + hw0;
            float* baseK = g_K + (size_t)bi * NCH * HW + hw0;
            float* baseQ = g_Q + (size_t)bi * NCH * HW + hw0;
            #pragma unroll
            for (int ms = 0; ms < 3; ms++) {
                #pragma unroll
                for (int half = 0; half < 2; half++) {
                    const int c = mrow0 + ms * 16 + g + half * 8;
                    float* p = c < 64 ? &baseV[(size_t)c * HW] :
                               c < 128 ? &baseK[(size_t)(c - 64) * HW]
                                       : &baseQ[(size_t)(c - 128) * HW];
                    #pragma unroll
                    for (int ns = 0; ns < 4; ns++) {
                        float2 o;
                        o.x = acc[ms][ns][half * 2 + 0];
                        o.y = acc[ms][ns][half * 2 + 1];
                        *(float2*)&p[ncol0 + ns * 8 + tig * 2] = o;
                    }
                }
            }
        }

        if (t + 1 < TPC) {
            CP_WAIT(0);
            __syncthreads();               // raw(t+1) fully arrived; MMA(t) done
            convert_n(rawp, XhB[(t + 1) & 1], XlB[(t + 1) & 1], tid);
            __syncthreads();               // tile(t+1) ready
        }
    }
}

// ---------------------------------------------------------------------------
// Kernel 2: gram + softmax.  One block of 128 per (b,c).
// K,Q arrive raw (bias included); apply SELU on load.
// ---------------------------------------------------------------------------
__global__ __launch_bounds__(128)
void gram_softmax_kernel()
{
    const int c = blockIdx.x;
    const int b = blockIdx.y;
    const int tid  = threadIdx.x;
    const int jg   = tid >> 5;
    const int lane = tid & 31;

    const float* Kb = g_K + ((size_t)b * ENS * NCH + c) * HW;
    const float* Qb = g_Q + ((size_t)b * ENS * NCH + c) * HW;

    float acc[16][4];
    #pragma unroll
    for (int i = 0; i < 16; i++)
        #pragma unroll
        for (int jj = 0; jj < 4; jj++) acc[i][jj] = 0.f;

    for (int it = 0; it < HW / 128; it++) {
        const int pos = (it * 32 + lane) * 4;
        float4 q[4];
        #pragma unroll
        for (int jj = 0; jj < 4; jj++) {
            int j = jg * 4 + jj;
            float4 r = *(const float4*)&Qb[(size_t)j * NCH * HW + pos];
            q[jj].x = selu_f(r.x); q[jj].y = selu_f(r.y);
            q[jj].z = selu_f(r.z); q[jj].w = selu_f(r.w);
        }
        #pragma unroll
        for (int i = 0; i < 16; i++) {
            float4 r = *(const float4*)&Kb[(size_t)i * NCH * HW + pos];
            float4 k4;
            k4.x = selu_f(r.x); k4.y = selu_f(r.y);
            k4.z = selu_f(r.z); k4.w = selu_f(r.w);
            #pragma unroll
            for (int jj = 0; jj < 4; jj++) {
                acc[i][jj] += k4.x * q[jj].x + k4.y * q[jj].y
                            + k4.z * q[jj].z + k4.w * q[jj].w;
            }
        }
    }

    __shared__ float sdots[16][16];
    #pragma unroll
    for (int i = 0; i < 16; i++)
        #pragma unroll
        for (int jj = 0; jj < 4; jj++) {
            float v = acc[i][jj];
            #pragma unroll
            for (int off = 16; off > 0; off >>= 1)
                v += __shfl_xor_sync(0xffffffffu, v, off);
            if (lane == 0) sdots[i][jg * 4 + jj] = v;
        }
    __syncthreads();

    if (tid < 16) {
        const int j = tid;
        float m = -INFINITY;
        #pragma unroll
        for (int i = 0; i < 16; i++) m = fmaxf(m, sdots[i][j]);
        float e[16], s = 0.f;
        #pragma unroll
        for (int i = 0; i < 16; i++) { e[i] = expf(sdots[i][j] - m); s += e[i]; }
        const float inv = 1.f / s;
        #pragma unroll
        for (int i = 0; i < 16; i++)
            g_Wgt[(((size_t)b * NCH + c) * ENS + i) * ENS + j] = e[i] * inv;
    }
}

// ---------------------------------------------------------------------------
// Kernel 3: mix + selu.  (mean-centering cancels via softmax)
// ---------------------------------------------------------------------------
__global__ __launch_bounds__(256)
void mix_kernel(float* __restrict__ out)
{
    const int tile = blockIdx.x;
    const int c    = blockIdx.y;
    const int b    = blockIdx.z;
    const int tid  = threadIdx.x;

    __shared__ float ws[16][16];
    ws[tid >> 4][tid & 15] = g_Wgt[((size_t)b * NCH + c) * 256 + tid];
    __syncthreads();

    const int pos = tile * 512 + tid * 2;
    const float* Vb = g_V + ((size_t)b * ENS * NCH + c) * HW + pos;
    float*       ob = out + ((size_t)b * ENS * NCH + c) * HW + pos;

    float2 v[16];
    #pragma unroll
    for (int i = 0; i < 16; i++)
        v[i] = *(const float2*)&Vb[(size_t)i * NCH * HW];

    #pragma unroll
    for (int j = 0; j < 16; j++) {
        float sx = 0.f, sy = 0.f;
        #pragma unroll
        for (int i = 0; i < 16; i++) {
            float w = ws[i][j];
            sx += w * v[i].x;
            sy += w * v[i].y;
        }
        float2 o; o.x = selu_f(sx); o.y = selu_f(sy);
        *(float2*)&ob[(size_t)j * NCH * HW] = o;
    }
}

// ---------------------------------------------------------------------------
extern "C" void kernel_launch(void* const* d_in, const int* in_sizes, int n_in,
                              void* d_out, int out_size)
{
    const float* x  = (const float*)d_in[0];
    const float* Wv = (const float*)d_in[1];
    const float* bv = (const float*)d_in[2];
    const float* Wk = (const float*)d_in[3];
    const float* bk = (const float*)d_in[4];
    const float* Wq = (const float*)d_in[5];
    const float* bq = (const float*)d_in[6];
    float* out = (float*)d_out;

    cudaFuncSetAttribute(conv3_mma_kernel,
                         cudaFuncAttributeMaxDynamicSharedMemorySize, SMEM_BYTES);

    prep_kernel<<<1, 512>>>(Wv, bv, Wk, bk, Wq, bq);

    dim3 g1(NBI, (HW / 128) / TPC);   // (128, 8)
    conv3_mma_kernel<<<g1, THREADS, SMEM_BYTES>>>(x);

    dim3 g2(NCH, BATCH);
    gram_softmax_kernel<<<g2, 128>>>();

    dim3 g3(HW / 512, NCH, BATCH);
    mix_kernel<<<g3, 256>>>(out);
}

// round 13
// speedup vs baseline: 1.7843x; 1.7843x over previous
#include <cuda_runtime.h>
#include <cuda_fp16.h>
#include <math.h>
#include <stdint.h>
#include <string.h>

// Problem dims
#define BATCH 8
#define ENS   16
#define NCIN  64
#define NCH   64
#define HW    4096
#define NBI   (BATCH*ENS)          // 128
#define NELEM ((size_t)NBI*NCH*HW) // 33,554,432

// Scratch (static device arrays -- allocation-free)
__device__ float g_V[NELEM];
__device__ float g_K[NELEM];
__device__ float g_Q[NELEM];
__device__ float g_Wgt[BATCH*NCH*ENS*ENS]; // softmaxed weights [b,c,i,j]

#define W_STRIDE   36    // half2 per W row (32 kpairs + pad)
__device__ __half2 g_Wh[192 * W_STRIDE];   // prepacked SMEM image (hi)
__device__ __half2 g_Wl[192 * W_STRIDE];   // prepacked SMEM image (lo)
__device__ float   g_bias3[192];

__device__ __forceinline__ float selu_f(float x) {
    const float scale = 1.0507009873554805f;
    const float alpha = 1.6732632423543772f;
    return x > 0.f ? scale * x : scale * alpha * expm1f(x);
}

__device__ __forceinline__ uint32_t h2u(__half2 v) {
    uint32_t r;
    memcpy(&r, &v, sizeof(r));
    return r;
}

__device__ __forceinline__ uint32_t smem_u32(const void* p) {
    return (uint32_t)__cvta_generic_to_shared(p);
}
__device__ __forceinline__ void cp16(void* dst_smem, const void* src) {
    uint32_t d = smem_u32(dst_smem);
    asm volatile("cp.async.cg.shared.global [%0], [%1], 16;" :: "r"(d), "l"(src));
}
#define CP_COMMIT()  asm volatile("cp.async.commit_group;" ::: "memory")
#define CP_WAIT(n)   asm volatile("cp.async.wait_group %0;" :: "n"(n) : "memory")

// fp16 MMA m16n8k16 (baseline PTX, valid on sm_103 non-'a' target)
__device__ __forceinline__ void mma_f16(float* c,
                                        uint32_t a0, uint32_t a1, uint32_t a2, uint32_t a3,
                                        uint32_t b0, uint32_t b1)
{
    asm volatile(
        "mma.sync.aligned.m16n8k16.row.col.f32.f16.f16.f32 "
        "{%0,%1,%2,%3}, {%4,%5,%6,%7}, {%8,%9}, {%0,%1,%2,%3};"
        : "+f"(c[0]), "+f"(c[1]), "+f"(c[2]), "+f"(c[3])
        : "r"(a0), "r"(a1), "r"(a2), "r"(a3), "r"(b0), "r"(b1));
}

// ldmatrix x4 (non-trans), baseline sm_75+ PTX
__device__ __forceinline__ void ldsm_x4(uint32_t& r0, uint32_t& r1,
                                        uint32_t& r2, uint32_t& r3, uint32_t addr)
{
    asm volatile("ldmatrix.sync.aligned.m8n8.x4.shared.b16 {%0,%1,%2,%3}, [%4];"
                 : "=r"(r0), "=r"(r1), "=r"(r2), "=r"(r3) : "r"(addr));
}

// ===========================================================================
// Kernel 0: prep — W3 fp16 hi/lo split into the exact SMEM image + bias.
// ===========================================================================
__global__ __launch_bounds__(512)
void prep_kernel(const float* __restrict__ Wv, const float* __restrict__ bv,
                 const float* __restrict__ Wk, const float* __restrict__ bk,
                 const float* __restrict__ Wq, const float* __restrict__ bq)
{
    const int tid = threadIdx.x;
    if (tid < 192) {
        g_bias3[tid] = tid < 64 ? bv[tid] : (tid < 128 ? bk[tid - 64] : bq[tid - 128]);
    }
    // zero pads for determinism
    #pragma unroll
    for (int j = 0; j < 2; j++) {
        int p = tid + j * 512;                // 192*4 = 768 pad half2s
        if (p < 192 * 4) {
            int n = p >> 2, k = p & 3;
            g_Wh[n * W_STRIDE + 32 + k] = __floats2half2_rn(0.f, 0.f);
            g_Wl[n * W_STRIDE + 32 + k] = __floats2half2_rn(0.f, 0.f);
        }
    }
    #pragma unroll
    for (int j = 0; j < 12; j++) {
        int idx = tid + j * 512;              // 6144 kpairs
        int n = idx >> 5, kp = idx & 31;
        const float* Wsrc = n < 64 ? &Wv[n * NCIN] :
                            n < 128 ? &Wk[(n - 64) * NCIN] : &Wq[(n - 128) * NCIN];
        float w0 = Wsrc[kp * 2], w1 = Wsrc[kp * 2 + 1];
        __half2 h = __floats2half2_rn(w0, w1);
        __half2 l = __floats2half2_rn(w0 - __low2float(h), w1 - __high2float(h));
        g_Wh[n * W_STRIDE + kp] = h;
        g_Wl[n * W_STRIDE + kp] = l;
    }
}

// ===========================================================================
// Kernel 1: fused 3-conv via FP16-split (2-way) mma.sync m16n8k16 + ldmatrix.
// Per (b,i): Out[192 ch, 4096 hw] = W3[192,64] @ X[64,4096]
// Bias folded into accumulator init; SELU applied in epilogue for K/Q.
// CTA: 512 thr (16 warps, 4m x 4n), tile 192 x 128 hw, TPC hw-tiles per CTA.
// ===========================================================================
#define THREADS    512
#define TPC        4
#define XN_STRIDE  36    // half2 per X n-row
#define RAW_STRIDE 132   // float per raw X cin-row

// SMEM byte offsets
#define OFF_WH    0                              // 192*36*4 = 27648
#define OFF_WL    27648
#define OFF_RAW   55296                          // 64*132*4 = 33792
#define OFF_XH0   89088                          // 128*36*4 = 18432
#define OFF_XL0   107520
#define OFF_XH1   125952
#define OFF_XL1   144384
#define OFF_BIAS  162816                         // 192*4
#define SMEM_BYTES 163584
#define XL_DELTA  (OFF_XL0 - OFF_XH0)            // 18432

// Issue this thread's cp.asyncs for one X tile (row-major raw staging)
__device__ __forceinline__ void stage_tile(float* __restrict__ rawp,
                                           const float* __restrict__ xb,
                                           int hw0, int tid)
{
    #pragma unroll
    for (int j = 0; j < 2; j++) {
        int u = tid + j * THREADS;         // 1024 (kp, c4) units
        int kp = u >> 5, c4 = u & 31;
        cp16(&rawp[(2 * kp) * RAW_STRIDE + c4 * 4],
             xb + (size_t)(2 * kp) * HW + hw0 + c4 * 4);
        cp16(&rawp[(2 * kp + 1) * RAW_STRIDE + c4 * 4],
             xb + (size_t)(2 * kp + 1) * HW + hw0 + c4 * 4);
    }
    CP_COMMIT();
}

// Convert raw [64 cin][128 hw] fp32 -> n-major hi/lo fp16.
__device__ __forceinline__ void convert_n(const float* __restrict__ rawp,
                                          __half2* __restrict__ Xh,
                                          __half2* __restrict__ Xl,
                                          int tid)
{
    #pragma unroll
    for (int j = 0; j < 2; j++) {
        int u = tid + j * THREADS;         // 1024 units
        int n = u & 127, kpb = u >> 7;
        const float* col = rawp + (size_t)(8 * kpb) * RAW_STRIDE + n;
        float r0 = col[0 * RAW_STRIDE], r1 = col[1 * RAW_STRIDE];
        float r2 = col[2 * RAW_STRIDE], r3 = col[3 * RAW_STRIDE];
        float r4 = col[4 * RAW_STRIDE], r5 = col[5 * RAW_STRIDE];
        float r6 = col[6 * RAW_STRIDE], r7 = col[7 * RAW_STRIDE];
        __half2 h0 = __floats2half2_rn(r0, r1);
        __half2 h1 = __floats2half2_rn(r2, r3);
        __half2 h2 = __floats2half2_rn(r4, r5);
        __half2 h3 = __floats2half2_rn(r6, r7);
        __half2 l0 = __floats2half2_rn(r0 - __low2float(h0), r1 - __high2float(h0));
        __half2 l1 = __floats2half2_rn(r2 - __low2float(h1), r3 - __high2float(h1));
        __half2 l2 = __floats2half2_rn(r4 - __low2float(h2), r5 - __high2float(h2));
        __half2 l3 = __floats2half2_rn(r6 - __low2float(h3), r7 - __high2float(h3));
        *(uint4*)&Xh[n * XN_STRIDE + 4 * kpb] =
            make_uint4(h2u(h0), h2u(h1), h2u(h2), h2u(h3));
        *(uint4*)&Xl[n * XN_STRIDE + 4 * kpb] =
            make_uint4(h2u(l0), h2u(l1), h2u(l2), h2u(l3));
    }
}

__global__ __launch_bounds__(THREADS, 1)
void conv3_mma_kernel(const float* __restrict__ x)
{
    extern __shared__ char smem[];
    const uint32_t sbase = smem_u32(smem);
    float*   rawp = (float*)(smem + OFF_RAW);
    __half2* XhB[2] = { (__half2*)(smem + OFF_XH0), (__half2*)(smem + OFF_XH1) };
    __half2* XlB[2] = { (__half2*)(smem + OFF_XL0), (__half2*)(smem + OFF_XL1) };
    float*   sbias = (float*)(smem + OFF_BIAS);

    const int tid  = threadIdx.x;
    const int wid  = tid >> 5;
    const int lane = tid & 31;
    const int g    = lane >> 2;     // groupID
    const int tig  = lane & 3;      // threadID_in_group

    const int bi = blockIdx.x;      // 0..127
    const int tg = blockIdx.y;      // 0..7
    const float* xb = x + (size_t)bi * NCIN * HW;

    // ---- stage tile0 ----
    stage_tile(rawp, xb, tg * TPC * 128, tid);

    // ---- async-copy prepacked W images + bias into SMEM ----
    {
        const float4* srcH = (const float4*)g_Wh;
        const float4* srcL = (const float4*)g_Wl;
        char* dstH = smem + OFF_WH;
        char* dstL = smem + OFF_WL;
        #pragma unroll
        for (int j = 0; j < 4; j++) {
            int idx = tid + j * THREADS;       // 1728 float4 per image
            if (idx < 1728) {
                cp16(dstH + idx * 16, srcH + idx);
                cp16(dstL + idx * 16, srcL + idx);
            }
        }
        if (tid < 48) cp16(smem + OFF_BIAS + tid * 16, (const float4*)g_bias3 + tid);
        CP_COMMIT();
    }

    CP_WAIT(0);
    __syncthreads();                           // staging + W + bias complete
    convert_n(rawp, XhB[0], XlB[0], tid);
    __syncthreads();                           // tile0 hi/lo ready

    const int mrow0 = (wid & 3) * 48;   // warp channel-rows base (3 x m16)
    const int ncol0 = (wid >> 2) * 32;  // warp hw-cols base (4 x n8)

    // per-thread bias registers for accumulator init
    float b_lo[3], b_hi[3];
    #pragma unroll
    for (int ms = 0; ms < 3; ms++) {
        b_lo[ms] = sbias[mrow0 + ms * 16 + g];
        b_hi[ms] = sbias[mrow0 + ms * 16 + 8 + g];
    }

    // ---- precomputed ldmatrix addresses (bytes) ----
    const int rowA_off = ((lane >> 3) & 1) * 8 + (lane & 7);
    const int kpA      = (lane >> 4) * 4;
    uint32_t addrAh[3], addrAl[3];
    #pragma unroll
    for (int ms = 0; ms < 3; ms++) {
        int row = mrow0 + ms * 16 + rowA_off;
        addrAh[ms] = sbase + OFF_WH + (uint32_t)(row * W_STRIDE + kpA) * 4;
        addrAl[ms] = addrAh[ms] + (OFF_WL - OFF_WH);
    }
    const int nB_off = ((lane >> 4) & 1) * 8 + (lane & 7);
    const int kpB    = ((lane >> 3) & 1) * 4;
    uint32_t relB[2];
    #pragma unroll
    for (int p = 0; p < 2; p++) {
        int n = ncol0 + p * 16 + nB_off;
        relB[p] = (uint32_t)(n * XN_STRIDE + kpB) * 4;
    }

    for (int t = 0; t < TPC; t++) {
        const int hw0 = (tg * TPC + t) * 128;

        // prefetch next raw tile (overlaps with MMA below)
        if (t + 1 < TPC) stage_tile(rawp, xb, hw0 + 128, tid);

        const uint32_t xh_base = sbase + ((t & 1) ? OFF_XH1 : OFF_XH0);
        const uint32_t xl_base = xh_base + XL_DELTA;

        // accumulators pre-loaded with bias (MMA accumulates on top)
        float acc[3][4][4];
        #pragma unroll
        for (int ms = 0; ms < 3; ms++)
            #pragma unroll
            for (int ns = 0; ns < 4; ns++) {
                acc[ms][ns][0] = b_lo[ms]; acc[ms][ns][1] = b_lo[ms];
                acc[ms][ns][2] = b_hi[ms]; acc[ms][ns][3] = b_hi[ms];
            }

        #pragma unroll
        for (int ks = 0; ks < 4; ks++) {
            const uint32_t ko = (uint32_t)ks * 32;   // 8 half2 per ks
            uint32_t bh[4][2], bl[4][2];
            ldsm_x4(bh[0][0], bh[0][1], bh[1][0], bh[1][1], xh_base + relB[0] + ko);
            ldsm_x4(bh[2][0], bh[2][1], bh[3][0], bh[3][1], xh_base + relB[1] + ko);
            ldsm_x4(bl[0][0], bl[0][1], bl[1][0], bl[1][1], xl_base + relB[0] + ko);
            ldsm_x4(bl[2][0], bl[2][1], bl[3][0], bl[3][1], xl_base + relB[1] + ko);

            #pragma unroll
            for (int ms = 0; ms < 3; ms++) {
                uint32_t ah0, ah1, ah2, ah3, al0, al1, al2, al3;
                ldsm_x4(ah0, ah1, ah2, ah3, addrAh[ms] + ko);
                ldsm_x4(al0, al1, al2, al3, addrAl[ms] + ko);
                #pragma unroll
                for (int ns = 0; ns < 4; ns++) {
                    mma_f16(acc[ms][ns], ah0, ah1, ah2, ah3, bh[ns][0], bh[ns][1]);
                    mma_f16(acc[ms][ns], ah0, ah1, ah2, ah3, bl[ns][0], bl[ns][1]);
                    mma_f16(acc[ms][ns], al0, al1, al2, al3, bh[ns][0], bh[ns][1]);
                }
            }
        }

        // ---- epilogue: selu for K/Q (bias already in acc), float2 stores ----
        {
            float* baseV = g_V + (size_t)bi * NCH * HW + hw0;
            float* baseK = g_K + (size_t)bi * NCH * HW + hw0;
            float* baseQ = g_Q + (size_t)bi * NCH * HW + hw0;
            #pragma unroll
            for (int ms = 0; ms < 3; ms++) {
                #pragma unroll
                for (int half = 0; half < 2; half++) {
                    const int c = mrow0 + ms * 16 + g + half * 8;
                    #pragma unroll
                    for (int ns = 0; ns < 4; ns++) {
                        const int col = ncol0 + ns * 8 + tig * 2;
                        float v0 = acc[ms][ns][half * 2 + 0];
                        float v1 = acc[ms][ns][half * 2 + 1];
                        float2 o;
                        if (c < 64) {
                            o.x = v0; o.y = v1;
                            *(float2*)&baseV[(size_t)c * HW + col] = o;
                        } else if (c < 128) {
                            o.x = selu_f(v0); o.y = selu_f(v1);
                            *(float2*)&baseK[(size_t)(c - 64) * HW + col] = o;
                        } else {
                            o.x = selu_f(v0); o.y = selu_f(v1);
                            *(float2*)&baseQ[(size_t)(c - 128) * HW + col] = o;
                        }
                    }
                }
            }
        }

        if (t + 1 < TPC) {
            CP_WAIT(0);
            __syncthreads();               // raw(t+1) fully arrived; MMA(t) done
            convert_n(rawp, XhB[(t + 1) & 1], XlB[(t + 1) & 1], tid);
            __syncthreads();               // tile(t+1) ready
        }
    }
}

// ---------------------------------------------------------------------------
// Kernel 2: gram + softmax.  One block of 128 per (b,c).  (R8-proven)
// ---------------------------------------------------------------------------
__global__ __launch_bounds__(128)
void gram_softmax_kernel()
{
    const int c = blockIdx.x;
    const int b = blockIdx.y;
    const int tid  = threadIdx.x;
    const int jg   = tid >> 5;
    const int lane = tid & 31;

    const float* Kb = g_K + ((size_t)b * ENS * NCH + c) * HW;
    const float* Qb = g_Q + ((size_t)b * ENS * NCH + c) * HW;

    float acc[16][4];
    #pragma unroll
    for (int i = 0; i < 16; i++)
        #pragma unroll
        for (int jj = 0; jj < 4; jj++) acc[i][jj] = 0.f;

    for (int it = 0; it < HW / 128; it++) {
        const int pos = (it * 32 + lane) * 4;
        float4 q[4];
        #pragma unroll
        for (int jj = 0; jj < 4; jj++) {
            int j = jg * 4 + jj;
            q[jj] = *(const float4*)&Qb[(size_t)j * NCH * HW + pos];
        }
        #pragma unroll
        for (int i = 0; i < 16; i++) {
            float4 k4 = *(const float4*)&Kb[(size_t)i * NCH * HW + pos];
            #pragma unroll
            for (int jj = 0; jj < 4; jj++) {
                acc[i][jj] += k4.x * q[jj].x + k4.y * q[jj].y
                            + k4.z * q[jj].z + k4.w * q[jj].w;
            }
        }
    }

    __shared__ float sdots[16][16];
    #pragma unroll
    for (int i = 0; i < 16; i++)
        #pragma unroll
        for (int jj = 0; jj < 4; jj++) {
            float v = acc[i][jj];
            #pragma unroll
            for (int off = 16; off > 0; off >>= 1)
                v += __shfl_xor_sync(0xffffffffu, v, off);
            if (lane == 0) sdots[i][jg * 4 + jj] = v;
        }
    __syncthreads();

    if (tid < 16) {
        const int j = tid;
        float m = -INFINITY;
        #pragma unroll
        for (int i = 0; i < 16; i++) m = fmaxf(m, sdots[i][j]);
        float e[16], s = 0.f;
        #pragma unroll
        for (int i = 0; i < 16; i++) { e[i] = expf(sdots[i][j] - m); s += e[i]; }
        const float inv = 1.f / s;
        #pragma unroll
        for (int i = 0; i < 16; i++)
            g_Wgt[(((size_t)b * NCH + c) * ENS + i) * ENS + j] = e[i] * inv;
    }
}

// ---------------------------------------------------------------------------
// Kernel 3: mix + selu.  (R8-proven; mean-centering cancels via softmax)
// ---------------------------------------------------------------------------
__global__ __launch_bounds__(256)
void mix_kernel(float* __restrict__ out)
{
    const int tile = blockIdx.x;
    const int c    = blockIdx.y;
    const int b    = blockIdx.z;
    const int tid  = threadIdx.x;

    __shared__ float ws[16][16];
    ws[tid >> 4][tid & 15] = g_Wgt[((size_t)b * NCH + c) * 256 + tid];
    __syncthreads();

    const int pos = tile * 512 + tid * 2;
    const float* Vb = g_V + ((size_t)b * ENS * NCH + c) * HW + pos;
    float*       ob = out + ((size_t)b * ENS * NCH + c) * HW + pos;

    float2 v[16];
    #pragma unroll
    for (int i = 0; i < 16; i++)
        v[i] = *(const float2*)&Vb[(size_t)i * NCH * HW];

    #pragma unroll
    for (int j = 0; j < 16; j++) {
        float sx = 0.f, sy = 0.f;
        #pragma unroll
        for (int i = 0; i < 16; i++) {
            float w = ws[i][j];
            sx += w * v[i].x;
            sy += w * v[i].y;
        }
        float2 o; o.x = selu_f(sx); o.y = selu_f(sy);
        *(float2*)&ob[(size_t)j * NCH * HW] = o;
    }
}

// ---------------------------------------------------------------------------
extern "C" void kernel_launch(void* const* d_in, const int* in_sizes, int n_in,
                              void* d_out, int out_size)
{
    const float* x  = (const float*)d_in[0];
    const float* Wv = (const float*)d_in[1];
    const float* bv = (const float*)d_in[2];
    const float* Wk = (const float*)d_in[3];
    const float* bk = (const float*)d_in[4];
    const float* Wq = (const float*)d_in[5];
    const float* bq = (const float*)d_in[6];
    float* out = (float*)d_out;

    cudaFuncSetAttribute(conv3_mma_kernel,
                         cudaFuncAttributeMaxDynamicSharedMemorySize, SMEM_BYTES);

    prep_kernel<<<1, 512>>>(Wv, bv, Wk, bk, Wq, bq);

    dim3 g1(NBI, (HW / 128) / TPC);   // (128, 8)
    conv3_mma_kernel<<<g1, THREADS, SMEM_BYTES>>>(x);

    dim3 g2(NCH, BATCH);
    gram_softmax_kernel<<<g2, 128>>>();

    dim3 g3(HW / 512, NCH, BATCH);
    mix_kernel<<<g3, 256>>>(out);
}

// round 14
// speedup vs baseline: 2.1207x; 1.1885x over previous
#include <cuda_runtime.h>
#include <cuda_fp16.h>
#include <math.h>
#include <stdint.h>
#include <string.h>

// Problem dims
#define BATCH 8
#define ENS   16
#define NCIN  64
#define NCH   64
#define HW    4096
#define NBI   (BATCH*ENS)          // 128
#define NELEM ((size_t)NBI*NCH*HW) // 33,554,432

// Scratch (static device arrays -- allocation-free)
__device__ float g_V[NELEM];
__device__ float g_K[NELEM];
__device__ float g_Q[NELEM];
__device__ float g_Wgt[BATCH*NCH*ENS*ENS]; // softmaxed weights [b,c,i,j]

#define W_STRIDE   36    // half2 per W row (32 kpairs + pad)
__device__ __half2 g_Wh[192 * W_STRIDE];   // prepacked SMEM image (hi)
__device__ __half2 g_Wl[192 * W_STRIDE];   // prepacked SMEM image (lo)
__device__ float   g_bias3[192];

// Fast SELU: __expf (MUFU.EX2) instead of expm1f. abs err ~2^-22, fine at 1e-3.
__device__ __forceinline__ float selu_f(float x) {
    const float scale = 1.0507009873554805f;
    const float salpha = 1.7580993408473766f;  // scale * alpha
    return x > 0.f ? scale * x : salpha * (__expf(x) - 1.f);
}

__device__ __forceinline__ uint32_t h2u(__half2 v) {
    uint32_t r;
    memcpy(&r, &v, sizeof(r));
    return r;
}

__device__ __forceinline__ uint32_t smem_u32(const void* p) {
    return (uint32_t)__cvta_generic_to_shared(p);
}
__device__ __forceinline__ void cp16(void* dst_smem, const void* src) {
    uint32_t d = smem_u32(dst_smem);
    asm volatile("cp.async.cg.shared.global [%0], [%1], 16;" :: "r"(d), "l"(src));
}
#define CP_COMMIT()  asm volatile("cp.async.commit_group;" ::: "memory")
#define CP_WAIT(n)   asm volatile("cp.async.wait_group %0;" :: "n"(n) : "memory")

// fp16 MMA m16n8k16 (baseline PTX, valid on sm_103 non-'a' target)
__device__ __forceinline__ void mma_f16(float* c,
                                        uint32_t a0, uint32_t a1, uint32_t a2, uint32_t a3,
                                        uint32_t b0, uint32_t b1)
{
    asm volatile(
        "mma.sync.aligned.m16n8k16.row.col.f32.f16.f16.f32 "
        "{%0,%1,%2,%3}, {%4,%5,%6,%7}, {%8,%9}, {%0,%1,%2,%3};"
        : "+f"(c[0]), "+f"(c[1]), "+f"(c[2]), "+f"(c[3])
        : "r"(a0), "r"(a1), "r"(a2), "r"(a3), "r"(b0), "r"(b1));
}

// ldmatrix x4 (non-trans), baseline sm_75+ PTX
__device__ __forceinline__ void ldsm_x4(uint32_t& r0, uint32_t& r1,
                                        uint32_t& r2, uint32_t& r3, uint32_t addr)
{
    asm volatile("ldmatrix.sync.aligned.m8n8.x4.shared.b16 {%0,%1,%2,%3}, [%4];"
                 : "=r"(r0), "=r"(r1), "=r"(r2), "=r"(r3) : "r"(addr));
}

// Packed f32x2 FMA (Blackwell FFMA2; PTX fma.rn.f32x2, sm_100+)
__device__ __forceinline__ void fma_x2(uint64_t& d, uint64_t a, uint64_t b)
{
    asm("fma.rn.f32x2 %0, %1, %2, %3;" : "=l"(d) : "l"(a), "l"(b), "l"(d));
}

// ===========================================================================
// Kernel 0: prep — W3 fp16 hi/lo split into the exact SMEM image + bias.
// ===========================================================================
__global__ __launch_bounds__(512)
void prep_kernel(const float* __restrict__ Wv, const float* __restrict__ bv,
                 const float* __restrict__ Wk, const float* __restrict__ bk,
                 const float* __restrict__ Wq, const float* __restrict__ bq)
{
    const int tid = threadIdx.x;
    if (tid < 192) {
        g_bias3[tid] = tid < 64 ? bv[tid] : (tid < 128 ? bk[tid - 64] : bq[tid - 128]);
    }
    // zero pads for determinism
    #pragma unroll
    for (int j = 0; j < 2; j++) {
        int p = tid + j * 512;                // 192*4 = 768 pad half2s
        if (p < 192 * 4) {
            int n = p >> 2, k = p & 3;
            g_Wh[n * W_STRIDE + 32 + k] = __floats2half2_rn(0.f, 0.f);
            g_Wl[n * W_STRIDE + 32 + k] = __floats2half2_rn(0.f, 0.f);
        }
    }
    #pragma unroll
    for (int j = 0; j < 12; j++) {
        int idx = tid + j * 512;              // 6144 kpairs
        int n = idx >> 5, kp = idx & 31;
        const float* Wsrc = n < 64 ? &Wv[n * NCIN] :
                            n < 128 ? &Wk[(n - 64) * NCIN] : &Wq[(n - 128) * NCIN];
        float w0 = Wsrc[kp * 2], w1 = Wsrc[kp * 2 + 1];
        __half2 h = __floats2half2_rn(w0, w1);
        __half2 l = __floats2half2_rn(w0 - __low2float(h), w1 - __high2float(h));
        g_Wh[n * W_STRIDE + kp] = h;
        g_Wl[n * W_STRIDE + kp] = l;
    }
}

// ===========================================================================
// Kernel 1: fused 3-conv via FP16-split (2-way) mma.sync m16n8k16 + ldmatrix.
// Per (b,i): Out[192 ch, 4096 hw] = W3[192,64] @ X[64,4096]
// Bias folded into accumulator init; SELU applied in epilogue for K/Q.
// CTA: 512 thr (16 warps, 4m x 4n), tile 192 x 128 hw, TPC hw-tiles per CTA.
// ===========================================================================
#define THREADS    512
#define TPC        4
#define XN_STRIDE  36    // half2 per X n-row
#define RAW_STRIDE 132   // float per raw X cin-row

// SMEM byte offsets
#define OFF_WH    0                              // 192*36*4 = 27648
#define OFF_WL    27648
#define OFF_RAW   55296                          // 64*132*4 = 33792
#define OFF_XH0   89088                          // 128*36*4 = 18432
#define OFF_XL0   107520
#define OFF_XH1   125952
#define OFF_XL1   144384
#define OFF_BIAS  162816                         // 192*4
#define SMEM_BYTES 163584
#define XL_DELTA  (OFF_XL0 - OFF_XH0)            // 18432

// Issue this thread's cp.asyncs for one X tile (row-major raw staging)
__device__ __forceinline__ void stage_tile(float* __restrict__ rawp,
                                           const float* __restrict__ xb,
                                           int hw0, int tid)
{
    #pragma unroll
    for (int j = 0; j < 2; j++) {
        int u = tid + j * THREADS;         // 1024 (kp, c4) units
        int kp = u >> 5, c4 = u & 31;
        cp16(&rawp[(2 * kp) * RAW_STRIDE + c4 * 4],
             xb + (size_t)(2 * kp) * HW + hw0 + c4 * 4);
        cp16(&rawp[(2 * kp + 1) * RAW_STRIDE + c4 * 4],
             xb + (size_t)(2 * kp + 1) * HW + hw0 + c4 * 4);
    }
    CP_COMMIT();
}

// Convert raw [64 cin][128 hw] fp32 -> n-major hi/lo fp16.
__device__ __forceinline__ void convert_n(const float* __restrict__ rawp,
                                          __half2* __restrict__ Xh,
                                          __half2* __restrict__ Xl,
                                          int tid)
{
    #pragma unroll
    for (int j = 0; j < 2; j++) {
        int u = tid + j * THREADS;         // 1024 units
        int n = u & 127, kpb = u >> 7;
        const float* col = rawp + (size_t)(8 * kpb) * RAW_STRIDE + n;
        float r0 = col[0 * RAW_STRIDE], r1 = col[1 * RAW_STRIDE];
        float r2 = col[2 * RAW_STRIDE], r3 = col[3 * RAW_STRIDE];
        float r4 = col[4 * RAW_STRIDE], r5 = col[5 * RAW_STRIDE];
        float r6 = col[6 * RAW_STRIDE], r7 = col[7 * RAW_STRIDE];
        __half2 h0 = __floats2half2_rn(r0, r1);
        __half2 h1 = __floats2half2_rn(r2, r3);
        __half2 h2 = __floats2half2_rn(r4, r5);
        __half2 h3 = __floats2half2_rn(r6, r7);
        __half2 l0 = __floats2half2_rn(r0 - __low2float(h0), r1 - __high2float(h0));
        __half2 l1 = __floats2half2_rn(r2 - __low2float(h1), r3 - __high2float(h1));
        __half2 l2 = __floats2half2_rn(r4 - __low2float(h2), r5 - __high2float(h2));
        __half2 l3 = __floats2half2_rn(r6 - __low2float(h3), r7 - __high2float(h3));
        *(uint4*)&Xh[n * XN_STRIDE + 4 * kpb] =
            make_uint4(h2u(h0), h2u(h1), h2u(h2), h2u(h3));
        *(uint4*)&Xl[n * XN_STRIDE + 4 * kpb] =
            make_uint4(h2u(l0), h2u(l1), h2u(l2), h2u(l3));
    }
}

__global__ __launch_bounds__(THREADS, 1)
void conv3_mma_kernel(const float* __restrict__ x)
{
    extern __shared__ char smem[];
    const uint32_t sbase = smem_u32(smem);
    float*   rawp = (float*)(smem + OFF_RAW);
    __half2* XhB[2] = { (__half2*)(smem + OFF_XH0), (__half2*)(smem + OFF_XH1) };
    __half2* XlB[2] = { (__half2*)(smem + OFF_XL0), (__half2*)(smem + OFF_XL1) };
    float*   sbias = (float*)(smem + OFF_BIAS);

    const int tid  = threadIdx.x;
    const int wid  = tid >> 5;
    const int lane = tid & 31;
    const int g    = lane >> 2;     // groupID
    const int tig  = lane & 3;      // threadID_in_group

    const int bi = blockIdx.x;      // 0..127
    const int tg = blockIdx.y;      // 0..7
    const float* xb = x + (size_t)bi * NCIN * HW;

    // ---- stage tile0 ----
    stage_tile(rawp, xb, tg * TPC * 128, tid);

    // ---- async-copy prepacked W images + bias into SMEM ----
    {
        const float4* srcH = (const float4*)g_Wh;
        const float4* srcL = (const float4*)g_Wl;
        char* dstH = smem + OFF_WH;
        char* dstL = smem + OFF_WL;
        #pragma unroll
        for (int j = 0; j < 4; j++) {
            int idx = tid + j * THREADS;       // 1728 float4 per image
            if (idx < 1728) {
                cp16(dstH + idx * 16, srcH + idx);
                cp16(dstL + idx * 16, srcL + idx);
            }
        }
        if (tid < 48) cp16(smem + OFF_BIAS + tid * 16, (const float4*)g_bias3 + tid);
        CP_COMMIT();
    }

    CP_WAIT(0);
    __syncthreads();                           // staging + W + bias complete
    convert_n(rawp, XhB[0], XlB[0], tid);
    __syncthreads();                           // tile0 hi/lo ready

    const int mrow0 = (wid & 3) * 48;   // warp channel-rows base (3 x m16)
    const int ncol0 = (wid >> 2) * 32;  // warp hw-cols base (4 x n8)

    // per-thread bias registers for accumulator init
    float b_lo[3], b_hi[3];
    #pragma unroll
    for (int ms = 0; ms < 3; ms++) {
        b_lo[ms] = sbias[mrow0 + ms * 16 + g];
        b_hi[ms] = sbias[mrow0 + ms * 16 + 8 + g];
    }

    // ---- precomputed ldmatrix addresses (bytes) ----
    const int rowA_off = ((lane >> 3) & 1) * 8 + (lane & 7);
    const int kpA      = (lane >> 4) * 4;
    uint32_t addrAh[3], addrAl[3];
    #pragma unroll
    for (int ms = 0; ms < 3; ms++) {
        int row = mrow0 + ms * 16 + rowA_off;
        addrAh[ms] = sbase + OFF_WH + (uint32_t)(row * W_STRIDE + kpA) * 4;
        addrAl[ms] = addrAh[ms] + (OFF_WL - OFF_WH);
    }
    const int nB_off = ((lane >> 4) & 1) * 8 + (lane & 7);
    const int kpB    = ((lane >> 3) & 1) * 4;
    uint32_t relB[2];
    #pragma unroll
    for (int p = 0; p < 2; p++) {
        int n = ncol0 + p * 16 + nB_off;
        relB[p] = (uint32_t)(n * XN_STRIDE + kpB) * 4;
    }

    for (int t = 0; t < TPC; t++) {
        const int hw0 = (tg * TPC + t) * 128;

        // prefetch next raw tile (overlaps with MMA below)
        if (t + 1 < TPC) stage_tile(rawp, xb, hw0 + 128, tid);

        const uint32_t xh_base = sbase + ((t & 1) ? OFF_XH1 : OFF_XH0);
        const uint32_t xl_base = xh_base + XL_DELTA;

        // accumulators pre-loaded with bias (MMA accumulates on top)
        float acc[3][4][4];
        #pragma unroll
        for (int ms = 0; ms < 3; ms++)
            #pragma unroll
            for (int ns = 0; ns < 4; ns++) {
                acc[ms][ns][0] = b_lo[ms]; acc[ms][ns][1] = b_lo[ms];
                acc[ms][ns][2] = b_hi[ms]; acc[ms][ns][3] = b_hi[ms];
            }

        #pragma unroll
        for (int ks = 0; ks < 4; ks++) {
            const uint32_t ko = (uint32_t)ks * 32;   // 8 half2 per ks
            uint32_t bh[4][2], bl[4][2];
            ldsm_x4(bh[0][0], bh[0][1], bh[1][0], bh[1][1], xh_base + relB[0] + ko);
            ldsm_x4(bh[2][0], bh[2][1], bh[3][0], bh[3][1], xh_base + relB[1] + ko);
            ldsm_x4(bl[0][0], bl[0][1], bl[1][0], bl[1][1], xl_base + relB[0] + ko);
            ldsm_x4(bl[2][0], bl[2][1], bl[3][0], bl[3][1], xl_base + relB[1] + ko);

            #pragma unroll
            for (int ms = 0; ms < 3; ms++) {
                uint32_t ah0, ah1, ah2, ah3, al0, al1, al2, al3;
                ldsm_x4(ah0, ah1, ah2, ah3, addrAh[ms] + ko);
                ldsm_x4(al0, al1, al2, al3, addrAl[ms] + ko);
                #pragma unroll
                for (int ns = 0; ns < 4; ns++) {
                    mma_f16(acc[ms][ns], ah0, ah1, ah2, ah3, bh[ns][0], bh[ns][1]);
                    mma_f16(acc[ms][ns], ah0, ah1, ah2, ah3, bl[ns][0], bl[ns][1]);
                    mma_f16(acc[ms][ns], al0, al1, al2, al3, bh[ns][0], bh[ns][1]);
                }
            }
        }

        // ---- epilogue: selu for K/Q (bias already in acc), float2 stores ----
        {
            float* baseV = g_V + (size_t)bi * NCH * HW + hw0;
            float* baseK = g_K + (size_t)bi * NCH * HW + hw0;
            float* baseQ = g_Q + (size_t)bi * NCH * HW + hw0;
            #pragma unroll
            for (int ms = 0; ms < 3; ms++) {
                #pragma unroll
                for (int half = 0; half < 2; half++) {
                    const int c = mrow0 + ms * 16 + g + half * 8;
                    #pragma unroll
                    for (int ns = 0; ns < 4; ns++) {
                        const int col = ncol0 + ns * 8 + tig * 2;
                        float v0 = acc[ms][ns][half * 2 + 0];
                        float v1 = acc[ms][ns][half * 2 + 1];
                        float2 o;
                        if (c < 64) {
                            o.x = v0; o.y = v1;
                            *(float2*)&baseV[(size_t)c * HW + col] = o;
                        } else if (c < 128) {
                            o.x = selu_f(v0); o.y = selu_f(v1);
                            *(float2*)&baseK[(size_t)(c - 64) * HW + col] = o;
                        } else {
                            o.x = selu_f(v0); o.y = selu_f(v1);
                            *(float2*)&baseQ[(size_t)(c - 128) * HW + col] = o;
                        }
                    }
                }
            }
        }

        if (t + 1 < TPC) {
            CP_WAIT(0);
            __syncthreads();               // raw(t+1) fully arrived; MMA(t) done
            convert_n(rawp, XhB[(t + 1) & 1], XlB[(t + 1) & 1], tid);
            __syncthreads();               // tile(t+1) ready
        }
    }
}

// ---------------------------------------------------------------------------
// Kernel 2: gram + softmax.  One block of 128 per (b,c).  (R8-proven)
// ---------------------------------------------------------------------------
__global__ __launch_bounds__(128)
void gram_softmax_kernel()
{
    const int c = blockIdx.x;
    const int b = blockIdx.y;
    const int tid  = threadIdx.x;
    const int jg   = tid >> 5;
    const int lane = tid & 31;

    const float* Kb = g_K + ((size_t)b * ENS * NCH + c) * HW;
    const float* Qb = g_Q + ((size_t)b * ENS * NCH + c) * HW;

    float acc[16][4];
    #pragma unroll
    for (int i = 0; i < 16; i++)
        #pragma unroll
        for (int jj = 0; jj < 4; jj++) acc[i][jj] = 0.f;

    for (int it = 0; it < HW / 128; it++) {
        const int pos = (it * 32 + lane) * 4;
        float4 q[4];
        #pragma unroll
        for (int jj = 0; jj < 4; jj++) {
            int j = jg * 4 + jj;
            q[jj] = *(const float4*)&Qb[(size_t)j * NCH * HW + pos];
        }
        #pragma unroll
        for (int i = 0; i < 16; i++) {
            float4 k4 = *(const float4*)&Kb[(size_t)i * NCH * HW + pos];
            #pragma unroll
            for (int jj = 0; jj < 4; jj++) {
                acc[i][jj] += k4.x * q[jj].x + k4.y * q[jj].y
                            + k4.z * q[jj].z + k4.w * q[jj].w;
            }
        }
    }

    __shared__ float sdots[16][16];
    #pragma unroll
    for (int i = 0; i < 16; i++)
        #pragma unroll
        for (int jj = 0; jj < 4; jj++) {
            float v = acc[i][jj];
            #pragma unroll
            for (int off = 16; off > 0; off >>= 1)
                v += __shfl_xor_sync(0xffffffffu, v, off);
            if (lane == 0) sdots[i][jg * 4 + jj] = v;
        }
    __syncthreads();

    if (tid < 16) {
        const int j = tid;
        float m = -INFINITY;
        #pragma unroll
        for (int i = 0; i < 16; i++) m = fmaxf(m, sdots[i][j]);
        float e[16], s = 0.f;
        #pragma unroll
        for (int i = 0; i < 16; i++) { e[i] = expf(sdots[i][j] - m); s += e[i]; }
        const float inv = 1.f / s;
        #pragma unroll
        for (int i = 0; i < 16; i++)
            g_Wgt[(((size_t)b * NCH + c) * ENS + i) * ENS + j] = e[i] * inv;
    }
}

// ---------------------------------------------------------------------------
// Kernel 3: mix + selu via packed f32x2 FFMA.
// out[b,j,c,hw] = selu( sum_i w[b,c,i,j] * V[b,i,c,hw] )
// Thread handles 4 hw (two f32x2 lanes); weights duplicated {w,w} in SMEM.
// ---------------------------------------------------------------------------
__global__ __launch_bounds__(256)
void mix_kernel(float* __restrict__ out)
{
    const int tile = blockIdx.x;   // 0..3
    const int c    = blockIdx.y;
    const int b    = blockIdx.z;
    const int tid  = threadIdx.x;

    __shared__ uint64_t ws2[256];  // ws2[i*16+j] = {w,w}
    {
        uint32_t wb = __float_as_uint(g_Wgt[((size_t)b * NCH + c) * 256 + tid]);
        ws2[tid] = (uint64_t)wb | ((uint64_t)wb << 32);
    }
    __syncthreads();

    const int pos = tile * 1024 + tid * 4;
    const float* Vb = g_V + ((size_t)b * ENS * NCH + c) * HW + pos;
    float*       ob = out + ((size_t)b * ENS * NCH + c) * HW + pos;

    uint64_t v0[16], v1[16];
    #pragma unroll
    for (int i = 0; i < 16; i++) {
        ulonglong2 r = *(const ulonglong2*)&Vb[(size_t)i * NCH * HW];
        v0[i] = r.x; v1[i] = r.y;
    }

    #pragma unroll
    for (int j = 0; j < 16; j++) {
        uint64_t s0 = 0, s1 = 0;   // packed {0,0}
        #pragma unroll
        for (int i = 0; i < 16; i++) {
            uint64_t w = ws2[i * 16 + j];
            fma_x2(s0, w, v0[i]);
            fma_x2(s1, w, v1[i]);
        }
        float4 o;
        o.x = selu_f(__uint_as_float((uint32_t)s0));
        o.y = selu_f(__uint_as_float((uint32_t)(s0 >> 32)));
        o.z = selu_f(__uint_as_float((uint32_t)s1));
        o.w = selu_f(__uint_as_float((uint32_t)(s1 >> 32)));
        *(float4*)&ob[(size_t)j * NCH * HW] = o;
    }
}

// ---------------------------------------------------------------------------
extern "C" void kernel_launch(void* const* d_in, const int* in_sizes, int n_in,
                              void* d_out, int out_size)
{
    const float* x  = (const float*)d_in[0];
    const float* Wv = (const float*)d_in[1];
    const float* bv = (const float*)d_in[2];
    const float* Wk = (const float*)d_in[3];
    const float* bk = (const float*)d_in[4];
    const float* Wq = (const float*)d_in[5];
    const float* bq = (const float*)d_in[6];
    float* out = (float*)d_out;

    cudaFuncSetAttribute(conv3_mma_kernel,
                         cudaFuncAttributeMaxDynamicSharedMemorySize, SMEM_BYTES);

    prep_kernel<<<1, 512>>>(Wv, bv, Wk, bk, Wq, bq);

    dim3 g1(NBI, (HW / 128) / TPC);   // (128, 8)
    conv3_mma_kernel<<<g1, THREADS, SMEM_BYTES>>>(x);

    dim3 g2(NCH, BATCH);
    gram_softmax_kernel<<<g2, 128>>>();

    dim3 g3(HW / 1024, NCH, BATCH);   // (4, 64, 8)
    mix_kernel<<<g3, 256>>>(out);
}

// round 15
// speedup vs baseline: 2.2046x; 1.0396x over previous
#include <cuda_runtime.h>
#include <cuda_fp16.h>
#include <math.h>
#include <stdint.h>
#include <string.h>

// Problem dims
#define BATCH 8
#define ENS   16
#define NCIN  64
#define NCH   64
#define HW    4096
#define NBI   (BATCH*ENS)          // 128
#define NELEM ((size_t)NBI*NCH*HW) // 33,554,432

// Scratch (static device arrays -- allocation-free)
__device__ float g_V[NELEM];
__device__ float g_K[NELEM];
__device__ float g_Q[NELEM];
__device__ float g_Wgt[BATCH*NCH*ENS*ENS]; // softmaxed weights [b,c,i,j]

#define W_STRIDE   36    // half2 per W row (32 kpairs + pad)
__device__ __half2 g_Wh[192 * W_STRIDE];   // prepacked SMEM image (hi)
__device__ __half2 g_Wl[192 * W_STRIDE];   // prepacked SMEM image (lo)
__device__ float   g_bias3[192];

// Fast SELU: __expf (MUFU.EX2) instead of expm1f. abs err ~2^-22, fine at 1e-3.
__device__ __forceinline__ float selu_f(float x) {
    const float scale = 1.0507009873554805f;
    const float salpha = 1.7580993408473766f;  // scale * alpha
    return x > 0.f ? scale * x : salpha * (__expf(x) - 1.f);
}

__device__ __forceinline__ uint32_t h2u(__half2 v) {
    uint32_t r;
    memcpy(&r, &v, sizeof(r));
    return r;
}

__device__ __forceinline__ uint32_t smem_u32(const void* p) {
    return (uint32_t)__cvta_generic_to_shared(p);
}
__device__ __forceinline__ void cp16(void* dst_smem, const void* src) {
    uint32_t d = smem_u32(dst_smem);
    asm volatile("cp.async.cg.shared.global [%0], [%1], 16;" :: "r"(d), "l"(src));
}
#define CP_COMMIT()  asm volatile("cp.async.commit_group;" ::: "memory")
#define CP_WAIT(n)   asm volatile("cp.async.wait_group %0;" :: "n"(n) : "memory")

// fp16 MMA m16n8k16 (baseline PTX, valid on sm_103 non-'a' target)
__device__ __forceinline__ void mma_f16(float* c,
                                        uint32_t a0, uint32_t a1, uint32_t a2, uint32_t a3,
                                        uint32_t b0, uint32_t b1)
{
    asm volatile(
        "mma.sync.aligned.m16n8k16.row.col.f32.f16.f16.f32 "
        "{%0,%1,%2,%3}, {%4,%5,%6,%7}, {%8,%9}, {%0,%1,%2,%3};"
        : "+f"(c[0]), "+f"(c[1]), "+f"(c[2]), "+f"(c[3])
        : "r"(a0), "r"(a1), "r"(a2), "r"(a3), "r"(b0), "r"(b1));
}

// ldmatrix x4 (non-trans), baseline sm_75+ PTX
__device__ __forceinline__ void ldsm_x4(uint32_t& r0, uint32_t& r1,
                                        uint32_t& r2, uint32_t& r3, uint32_t addr)
{
    asm volatile("ldmatrix.sync.aligned.m8n8.x4.shared.b16 {%0,%1,%2,%3}, [%4];"
                 : "=r"(r0), "=r"(r1), "=r"(r2), "=r"(r3) : "r"(addr));
}

// Packed f32x2 FMA (Blackwell FFMA2; PTX fma.rn.f32x2, sm_100+)
__device__ __forceinline__ void fma_x2(uint64_t& d, uint64_t a, uint64_t b)
{
    asm("fma.rn.f32x2 %0, %1, %2, %3;" : "=l"(d) : "l"(a), "l"(b), "l"(d));
}

// ===========================================================================
// Kernel 0: prep — W3 fp16 hi/lo split into the exact SMEM image + bias.
// ===========================================================================
__global__ __launch_bounds__(512)
void prep_kernel(const float* __restrict__ Wv, const float* __restrict__ bv,
                 const float* __restrict__ Wk, const float* __restrict__ bk,
                 const float* __restrict__ Wq, const float* __restrict__ bq)
{
    const int tid = threadIdx.x;
    if (tid < 192) {
        g_bias3[tid] = tid < 64 ? bv[tid] : (tid < 128 ? bk[tid - 64] : bq[tid - 128]);
    }
    // zero pads for determinism
    #pragma unroll
    for (int j = 0; j < 2; j++) {
        int p = tid + j * 512;                // 192*4 = 768 pad half2s
        if (p < 192 * 4) {
            int n = p >> 2, k = p & 3;
            g_Wh[n * W_STRIDE + 32 + k] = __floats2half2_rn(0.f, 0.f);
            g_Wl[n * W_STRIDE + 32 + k] = __floats2half2_rn(0.f, 0.f);
        }
    }
    #pragma unroll
    for (int j = 0; j < 12; j++) {
        int idx = tid + j * 512;              // 6144 kpairs
        int n = idx >> 5, kp = idx & 31;
        const float* Wsrc = n < 64 ? &Wv[n * NCIN] :
                            n < 128 ? &Wk[(n - 64) * NCIN] : &Wq[(n - 128) * NCIN];
        float w0 = Wsrc[kp * 2], w1 = Wsrc[kp * 2 + 1];
        __half2 h = __floats2half2_rn(w0, w1);
        __half2 l = __floats2half2_rn(w0 - __low2float(h), w1 - __high2float(h));
        g_Wh[n * W_STRIDE + kp] = h;
        g_Wl[n * W_STRIDE + kp] = l;
    }
}

// ===========================================================================
// Kernel 1: fused 3-conv via FP16-split (2-way) mma.sync m16n8k16 + ldmatrix.
// Per (b,i): Out[192 ch, 4096 hw] = W3[192,64] @ X[64,4096]
// Bias folded into accumulator init; SELU in epilogue for K/Q.
// CTA: 512 thr (16 warps, 4m x 4n), tile 192 x 128 hw, TPC hw-tiles per CTA.
// Staging is WARP-SELF-CONSISTENT: each warp cp.asyncs exactly the raw chunks
// its own convert_n units read -> stage->convert ordering needs only
// CP_WAIT + __syncwarp (one full barrier per tile instead of two).
// ===========================================================================
#define THREADS    512
#define TPC        4
#define XN_STRIDE  36    // half2 per X n-row
#define RAW_STRIDE 132   // float per raw X cin-row

// SMEM byte offsets
#define OFF_WH    0                              // 192*36*4 = 27648
#define OFF_WL    27648
#define OFF_RAW   55296                          // 64*132*4 = 33792
#define OFF_XH0   89088                          // 128*36*4 = 18432
#define OFF_XL0   107520
#define OFF_XH1   125952
#define OFF_XL1   144384
#define OFF_BIAS  162816                         // 192*4
#define SMEM_BYTES 163584
#define XL_DELTA  (OFF_XL0 - OFF_XH0)            // 18432

// Warp-self-consistent staging: warp w owns cols [32*(w&3), +32) and cin rows
// [8*(w>>2), +8) plus [32+8*(w>>2), +8).  Lane l stages 4 16B chunks.
__device__ __forceinline__ void stage_tile(float* __restrict__ rawp,
                                           const float* __restrict__ xb,
                                           int hw0, int wid, int lane)
{
    const int col0 = 32 * (wid & 3);
    const int row0 = 8 * (wid >> 2);
    #pragma unroll
    for (int k = 0; k < 4; k++) {
        int ch = lane + 32 * k;            // 0..127
        int r  = ch >> 3;                  // 0..15
        int cc = ch & 7;                   // 16B chunk within 128B span
        int cin = (r < 8) ? (row0 + r) : (32 + row0 + (r - 8));
        int off = col0 + cc * 4;
        cp16(&rawp[cin * RAW_STRIDE + off],
             xb + (size_t)cin * HW + hw0 + off);
    }
    CP_COMMIT();
}

// Convert raw [64 cin][128 hw] fp32 -> n-major hi/lo fp16.
// Unit u: n = u&127, kpb = u>>7.  Warp w's units read exactly the region
// staged by stage_tile(w) above.
__device__ __forceinline__ void convert_n(const float* __restrict__ rawp,
                                          __half2* __restrict__ Xh,
                                          __half2* __restrict__ Xl,
                                          int tid)
{
    #pragma unroll
    for (int j = 0; j < 2; j++) {
        int u = tid + j * THREADS;         // 1024 units
        int n = u & 127, kpb = u >> 7;
        const float* col = rawp + (size_t)(8 * kpb) * RAW_STRIDE + n;
        float r0 = col[0 * RAW_STRIDE], r1 = col[1 * RAW_STRIDE];
        float r2 = col[2 * RAW_STRIDE], r3 = col[3 * RAW_STRIDE];
        float r4 = col[4 * RAW_STRIDE], r5 = col[5 * RAW_STRIDE];
        float r6 = col[6 * RAW_STRIDE], r7 = col[7 * RAW_STRIDE];
        __half2 h0 = __floats2half2_rn(r0, r1);
        __half2 h1 = __floats2half2_rn(r2, r3);
        __half2 h2 = __floats2half2_rn(r4, r5);
        __half2 h3 = __floats2half2_rn(r6, r7);
        __half2 l0 = __floats2half2_rn(r0 - __low2float(h0), r1 - __high2float(h0));
        __half2 l1 = __floats2half2_rn(r2 - __low2float(h1), r3 - __high2float(h1));
        __half2 l2 = __floats2half2_rn(r4 - __low2float(h2), r5 - __high2float(h2));
        __half2 l3 = __floats2half2_rn(r6 - __low2float(h3), r7 - __high2float(h3));
        *(uint4*)&Xh[n * XN_STRIDE + 4 * kpb] =
            make_uint4(h2u(h0), h2u(h1), h2u(h2), h2u(h3));
        *(uint4*)&Xl[n * XN_STRIDE + 4 * kpb] =
            make_uint4(h2u(l0), h2u(l1), h2u(l2), h2u(l3));
    }
}

__global__ __launch_bounds__(THREADS, 1)
void conv3_mma_kernel(const float* __restrict__ x)
{
    extern __shared__ char smem[];
    const uint32_t sbase = smem_u32(smem);
    float*   rawp = (float*)(smem + OFF_RAW);
    __half2* XhB[2] = { (__half2*)(smem + OFF_XH0), (__half2*)(smem + OFF_XH1) };
    __half2* XlB[2] = { (__half2*)(smem + OFF_XL0), (__half2*)(smem + OFF_XL1) };
    float*   sbias = (float*)(smem + OFF_BIAS);

    const int tid  = threadIdx.x;
    const int wid  = tid >> 5;
    const int lane = tid & 31;
    const int g    = lane >> 2;     // groupID
    const int tig  = lane & 3;      // threadID_in_group

    const int bi = blockIdx.x;      // 0..127
    const int tg = blockIdx.y;      // 0..7
    const float* xb = x + (size_t)bi * NCIN * HW;

    // ---- stage tile0 (warp-self-consistent) ----
    stage_tile(rawp, xb, tg * TPC * 128, wid, lane);

    // ---- async-copy prepacked W images + bias into SMEM ----
    {
        const float4* srcH = (const float4*)g_Wh;
        const float4* srcL = (const float4*)g_Wl;
        char* dstH = smem + OFF_WH;
        char* dstL = smem + OFF_WL;
        #pragma unroll
        for (int j = 0; j < 4; j++) {
            int idx = tid + j * THREADS;       // 1728 float4 per image
            if (idx < 1728) {
                cp16(dstH + idx * 16, srcH + idx);
                cp16(dstL + idx * 16, srcL + idx);
            }
        }
        if (tid < 48) cp16(smem + OFF_BIAS + tid * 16, (const float4*)g_bias3 + tid);
        CP_COMMIT();
    }

    CP_WAIT(0);                    // own cp.asyncs (tile0 chunks + W slices) done
    __syncwarp();
    convert_n(rawp, XhB[0], XlB[0], tid);      // reads only own warp's region
    __syncthreads();                           // W + bias + tile0 visible to all

    const int mrow0 = (wid & 3) * 48;   // warp channel-rows base (3 x m16)
    const int ncol0 = (wid >> 2) * 32;  // warp hw-cols base (4 x n8)

    // per-thread bias registers for accumulator init
    float b_lo[3], b_hi[3];
    #pragma unroll
    for (int ms = 0; ms < 3; ms++) {
        b_lo[ms] = sbias[mrow0 + ms * 16 + g];
        b_hi[ms] = sbias[mrow0 + ms * 16 + 8 + g];
    }

    // ---- precomputed ldmatrix addresses (bytes) ----
    const int rowA_off = ((lane >> 3) & 1) * 8 + (lane & 7);
    const int kpA      = (lane >> 4) * 4;
    uint32_t addrAh[3], addrAl[3];
    #pragma unroll
    for (int ms = 0; ms < 3; ms++) {
        int row = mrow0 + ms * 16 + rowA_off;
        addrAh[ms] = sbase + OFF_WH + (uint32_t)(row * W_STRIDE + kpA) * 4;
        addrAl[ms] = addrAh[ms] + (OFF_WL - OFF_WH);
    }
    const int nB_off = ((lane >> 4) & 1) * 8 + (lane & 7);
    const int kpB    = ((lane >> 3) & 1) * 4;
    uint32_t relB[2];
    #pragma unroll
    for (int p = 0; p < 2; p++) {
        int n = ncol0 + p * 16 + nB_off;
        relB[p] = (uint32_t)(n * XN_STRIDE + kpB) * 4;
    }

    for (int t = 0; t < TPC; t++) {
        const int hw0 = (tg * TPC + t) * 128;

        // prefetch next raw tile (overlaps with MMA below)
        if (t + 1 < TPC) stage_tile(rawp, xb, hw0 + 128, wid, lane);

        const uint32_t xh_base = sbase + ((t & 1) ? OFF_XH1 : OFF_XH0);
        const uint32_t xl_base = xh_base + XL_DELTA;

        // accumulators pre-loaded with bias (MMA accumulates on top)
        float acc[3][4][4];
        #pragma unroll
        for (int ms = 0; ms < 3; ms++)
            #pragma unroll
            for (int ns = 0; ns < 4; ns++) {
                acc[ms][ns][0] = b_lo[ms]; acc[ms][ns][1] = b_lo[ms];
                acc[ms][ns][2] = b_hi[ms]; acc[ms][ns][3] = b_hi[ms];
            }

        #pragma unroll
        for (int ks = 0; ks < 4; ks++) {
            const uint32_t ko = (uint32_t)ks * 32;   // 8 half2 per ks
            uint32_t bh[4][2], bl[4][2];
            ldsm_x4(bh[0][0], bh[0][1], bh[1][0], bh[1][1], xh_base + relB[0] + ko);
            ldsm_x4(bh[2][0], bh[2][1], bh[3][0], bh[3][1], xh_base + relB[1] + ko);
            ldsm_x4(bl[0][0], bl[0][1], bl[1][0], bl[1][1], xl_base + relB[0] + ko);
            ldsm_x4(bl[2][0], bl[2][1], bl[3][0], bl[3][1], xl_base + relB[1] + ko);

            #pragma unroll
            for (int ms = 0; ms < 3; ms++) {
                uint32_t ah0, ah1, ah2, ah3, al0, al1, al2, al3;
                ldsm_x4(ah0, ah1, ah2, ah3, addrAh[ms] + ko);
                ldsm_x4(al0, al1, al2, al3, addrAl[ms] + ko);
                #pragma unroll
                for (int ns = 0; ns < 4; ns++) {
                    mma_f16(acc[ms][ns], ah0, ah1, ah2, ah3, bh[ns][0], bh[ns][1]);
                    mma_f16(acc[ms][ns], ah0, ah1, ah2, ah3, bl[ns][0], bl[ns][1]);
                    mma_f16(acc[ms][ns], al0, al1, al2, al3, bh[ns][0], bh[ns][1]);
                }
            }
        }

        // ---- epilogue: selu for K/Q (bias already in acc), float2 stores ----
        {
            float* baseV = g_V + (size_t)bi * NCH * HW + hw0;
            float* baseK = g_K + (size_t)bi * NCH * HW + hw0;
            float* baseQ = g_Q + (size_t)bi * NCH * HW + hw0;
            #pragma unroll
            for (int ms = 0; ms < 3; ms++) {
                #pragma unroll
                for (int half = 0; half < 2; half++) {
                    const int c = mrow0 + ms * 16 + g + half * 8;
                    #pragma unroll
                    for (int ns = 0; ns < 4; ns++) {
                        const int col = ncol0 + ns * 8 + tig * 2;
                        float v0 = acc[ms][ns][half * 2 + 0];
                        float v1 = acc[ms][ns][half * 2 + 1];
                        float2 o;
                        if (c < 64) {
                            o.x = v0; o.y = v1;
                            *(float2*)&baseV[(size_t)c * HW + col] = o;
                        } else if (c < 128) {
                            o.x = selu_f(v0); o.y = selu_f(v1);
                            *(float2*)&baseK[(size_t)(c - 64) * HW + col] = o;
                        } else {
                            o.x = selu_f(v0); o.y = selu_f(v1);
                            *(float2*)&baseQ[(size_t)(c - 128) * HW + col] = o;
                        }
                    }
                }
            }
        }

        if (t + 1 < TPC) {
            CP_WAIT(0);                // own raw(t+1) chunks arrived
            __syncwarp();
            convert_n(rawp, XhB[(t + 1) & 1], XlB[(t + 1) & 1], tid);
            __syncthreads();           // tile(t+1) ready; all warps past MMA(t)
        }
    }
}

// ---------------------------------------------------------------------------
// Kernel 2: gram + softmax.  One block of 128 per (b,c).  (R8-proven)
// ---------------------------------------------------------------------------
__global__ __launch_bounds__(128)
void gram_softmax_kernel()
{
    const int c = blockIdx.x;
    const int b = blockIdx.y;
    const int tid  = threadIdx.x;
    const int jg   = tid >> 5;
    const int lane = tid & 31;

    const float* Kb = g_K + ((size_t)b * ENS * NCH + c) * HW;
    const float* Qb = g_Q + ((size_t)b * ENS * NCH + c) * HW;

    float acc[16][4];
    #pragma unroll
    for (int i = 0; i < 16; i++)
        #pragma unroll
        for (int jj = 0; jj < 4; jj++) acc[i][jj] = 0.f;

    for (int it = 0; it < HW / 128; it++) {
        const int pos = (it * 32 + lane) * 4;
        float4 q[4];
        #pragma unroll
        for (int jj = 0; jj < 4; jj++) {
            int j = jg * 4 + jj;
            q[jj] = *(const float4*)&Qb[(size_t)j * NCH * HW + pos];
        }
        #pragma unroll
        for (int i = 0; i < 16; i++) {
            float4 k4 = *(const float4*)&Kb[(size_t)i * NCH * HW + pos];
            #pragma unroll
            for (int jj = 0; jj < 4; jj++) {
                acc[i][jj] += k4.x * q[jj].x + k4.y * q[jj].y
                            + k4.z * q[jj].z + k4.w * q[jj].w;
            }
        }
    }

    __shared__ float sdots[16][16];
    #pragma unroll
    for (int i = 0; i < 16; i++)
        #pragma unroll
        for (int jj = 0; jj < 4; jj++) {
            float v = acc[i][jj];
            #pragma unroll
            for (int off = 16; off > 0; off >>= 1)
                v += __shfl_xor_sync(0xffffffffu, v, off);
            if (lane == 0) sdots[i][jg * 4 + jj] = v;
        }
    __syncthreads();

    if (tid < 16) {
        const int j = tid;
        float m = -INFINITY;
        #pragma unroll
        for (int i = 0; i < 16; i++) m = fmaxf(m, sdots[i][j]);
        float e[16], s = 0.f;
        #pragma unroll
        for (int i = 0; i < 16; i++) { e[i] = expf(sdots[i][j] - m); s += e[i]; }
        const float inv = 1.f / s;
        #pragma unroll
        for (int i = 0; i < 16; i++)
            g_Wgt[(((size_t)b * NCH + c) * ENS + i) * ENS + j] = e[i] * inv;
    }
}

// ---------------------------------------------------------------------------
// Kernel 3: mix + selu via packed f32x2 FFMA, 2 hw/thread (low regs, high occ).
// out[b,j,c,hw] = selu( sum_i w[b,c,i,j] * V[b,i,c,hw] )
// ---------------------------------------------------------------------------
__global__ __launch_bounds__(256)
void mix_kernel(float* __restrict__ out)
{
    const int tile = blockIdx.x;   // 0..7
    const int c    = blockIdx.y;
    const int b    = blockIdx.z;
    const int tid  = threadIdx.x;

    __shared__ uint64_t ws2[256];  // ws2[i*16+j] = {w,w}
    {
        uint32_t wb = __float_as_uint(g_Wgt[((size_t)b * NCH + c) * 256 + tid]);
        ws2[tid] = (uint64_t)wb | ((uint64_t)wb << 32);
    }
    __syncthreads();

    const int pos = tile * 512 + tid * 2;
    const float* Vb = g_V + ((size_t)b * ENS * NCH + c) * HW + pos;
    float*       ob = out + ((size_t)b * ENS * NCH + c) * HW + pos;

    uint64_t v[16];
    #pragma unroll
    for (int i = 0; i < 16; i++)
        v[i] = *(const uint64_t*)&Vb[(size_t)i * NCH * HW];

    #pragma unroll
    for (int j = 0; j < 16; j++) {
        uint64_t s = 0;            // packed {0,0}
        #pragma unroll
        for (int i = 0; i < 16; i++)
            fma_x2(s, ws2[i * 16 + j], v[i]);
        float2 o;
        o.x = selu_f(__uint_as_float((uint32_t)s));
        o.y = selu_f(__uint_as_float((uint32_t)(s >> 32)));
        *(float2*)&ob[(size_t)j * NCH * HW] = o;
    }
}

// ---------------------------------------------------------------------------
extern "C" void kernel_launch(void* const* d_in, const int* in_sizes, int n_in,
                              void* d_out, int out_size)
{
    const float* x  = (const float*)d_in[0];
    const float* Wv = (const float*)d_in[1];
    const float* bv = (const float*)d_in[2];
    const float* Wk = (const float*)d_in[3];
    const float* bk = (const float*)d_in[4];
    const float* Wq = (const float*)d_in[5];
    const float* bq = (const float*)d_in[6];
    float* out = (float*)d_out;

    cudaFuncSetAttribute(conv3_mma_kernel,
                         cudaFuncAttributeMaxDynamicSharedMemorySize, SMEM_BYTES);

    prep_kernel<<<1, 512>>>(Wv, bv, Wk, bk, Wq, bq);

    dim3 g1(NBI, (HW / 128) / TPC);   // (128, 8)
    conv3_mma_kernel<<<g1, THREADS, SMEM_BYTES>>>(x);

    dim3 g2(NCH, BATCH);
    gram_softmax_kernel<<<g2, 128>>>();

    dim3 g3(HW / 512, NCH, BATCH);    // (8, 64, 8)
    mix_kernel<<<g3, 256>>>(out);
}